// round 2
// baseline (speedup 1.0000x reference)
#include <cuda_runtime.h>
#include <cstddef>

// ---------------- device scratch (no allocations allowed) ----------------
#define MAX_N 262144
__device__ float    g_v[128];           // proj_w @ w_st
__device__ float    g_u[64];            // w_his2 @ w_st
__device__ float    g_U[16];            // user_out[b] + b_u + b_st
__device__ float    g_c;                // proj_b · w_st
__device__ float    g_bh2;              // b_his2 · w_st
__device__ float    g_delta[1 << 20];   // per-(b,n) scattered correction (4 MB)
__device__ unsigned g_flag[MAX_N];      // per-n batch bitmask (zero-init, spots reused)

// ---------------- K1: prep (block 0) + scattered zeroing (blocks 1..) ----------------
__global__ void prep_zero_kernel(const float* __restrict__ proj_w,
                                 const float* __restrict__ proj_b,
                                 const float* __restrict__ w_his2,
                                 const float* __restrict__ b_his2,
                                 const float* __restrict__ w_st,
                                 const float* __restrict__ b_st,
                                 const float* __restrict__ w_u,
                                 const float* __restrict__ b_u,
                                 const float* __restrict__ user_embedding,
                                 const float* __restrict__ user_emb_table,
                                 const float* __restrict__ theta,
                                 const int* __restrict__ user_id,
                                 const int* __restrict__ now_nodes,
                                 const int* __restrict__ his_nodes,
                                 int Bn, int N, int K, int BK)
{
    int tid = threadIdx.x;
    if (blockIdx.x == 0) {
        __shared__ float ws[128];
        if (tid < 128) ws[tid] = w_st[tid];
        __syncthreads();

        if (tid < 128) {
            float acc = 0.f;
            #pragma unroll 8
            for (int j = 0; j < 128; ++j) acc += proj_w[tid * 128 + j] * ws[j];
            g_v[tid] = acc;
        } else if (tid < 192) {
            int j = tid - 128;
            float acc = 0.f;
            #pragma unroll 8
            for (int d = 0; d < 128; ++d) acc += w_his2[j * 128 + d] * ws[d];
            g_u[j] = acc;
        } else if (tid < 192 + 16) {
            int b = tid - 192;
            if (b < Bn) {
                int uid = user_id[b];
                float th = theta[uid];
                float acc = 0.f;
                #pragma unroll 8
                for (int d = 0; d < 128; ++d) {
                    float um = (1.f - th) * user_embedding[b * 128 + d]
                             + th * user_emb_table[(size_t)uid * 128 + d];
                    acc += um * w_u[d];
                }
                g_U[b] = acc + b_u[0] + b_st[0];
            }
        } else if (tid == 208) {
            float acc = 0.f;
            for (int d = 0; d < 128; ++d) acc += proj_b[d] * ws[d];
            g_c = acc;
        } else if (tid == 209) {
            float acc = 0.f;
            for (int d = 0; d < 128; ++d) acc += b_his2[d] * ws[d];
            g_bh2 = acc;
        }
    } else {
        // zero the scattered delta/flag spots this run will touch (idempotent)
        int t = (blockIdx.x - 1) * blockDim.x + tid;
        if (t < 2 * BK) {
            int which = t / BK, r = t - which * BK;
            int n = which ? his_nodes[r] : now_nodes[r];
            int b = r / K;
            g_flag[n] = 0u;
            g_delta[(size_t)b * N + n] = 0.f;
        }
    }
}

// ---------------- K2: corrections into g_delta / g_flag ----------------
// blocks [0, hisBlocks): his MLP entries, w_his1 staged in smem, warp/entry.
// blocks [hisBlocks, ..): now dot-product entries, warp/entry.
__global__ __launch_bounds__(256)
void corr_kernel(const int* __restrict__ now_nodes,
                 const int* __restrict__ his_nodes,
                 const float* __restrict__ alpha,
                 const float* __restrict__ station_embedding,
                 const float* __restrict__ raw_field_embed,
                 const float* __restrict__ w_st,
                 const float* __restrict__ w_his1,
                 const float* __restrict__ b_his1,
                 int N, int K, int BK, int hisBlocks)
{
    __shared__ float w1s[128 * 64];      // 32 KB
    __shared__ float xs[8][128];
    int tid = threadIdx.x;
    int lane = tid & 31, warp = tid >> 5;

    if (blockIdx.x < hisBlocks) {
        for (int i = tid; i < 128 * 64; i += 256) w1s[i] = w_his1[i];
        __syncthreads();

        float b0 = b_his1[lane], b1 = b_his1[lane + 32];
        float u0 = g_u[lane],    u1 = g_u[lane + 32];
        float bh2 = g_bh2;

        #pragma unroll
        for (int i = 0; i < 4; ++i) {
            int e = blockIdx.x * 32 + warp * 4 + i;
            if (e >= BK) break;
            int n = his_nodes[e], b = e / K;
            float4 xv = reinterpret_cast<const float4*>(
                            raw_field_embed + (size_t)n * 128)[lane];
            reinterpret_cast<float4*>(xs[warp])[lane] = xv;
            __syncwarp();
            float a0 = b0, a1 = b1;
            #pragma unroll 8
            for (int d = 0; d < 128; ++d) {
                float x = xs[warp][d];
                a0 += x * w1s[d * 64 + lane];
                a1 += x * w1s[d * 64 + lane + 32];
            }
            float l0 = a0 > 0.f ? a0 : 0.01f * a0;
            float l1 = a1 > 0.f ? a1 : 0.01f * a1;
            float val = l0 * u0 + l1 * u1;
            #pragma unroll
            for (int off = 16; off; off >>= 1)
                val += __shfl_xor_sync(0xffffffffu, val, off);
            if (lane == 0) {
                atomicAdd(&g_delta[(size_t)b * N + n], alpha[n] * (val + bh2));
                atomicOr(&g_flag[n], 1u << b);
            }
            __syncwarp();
        }
    } else {
        int bb = blockIdx.x - hisBlocks;
        float4 w4 = reinterpret_cast<const float4*>(w_st)[lane];
        #pragma unroll
        for (int i = 0; i < 4; ++i) {
            int e = bb * 32 + warp * 4 + i;
            if (e >= BK) break;
            int n = now_nodes[e], b = e / K;
            float4 r = reinterpret_cast<const float4*>(
                           station_embedding + (size_t)n * 128)[lane];
            float p = r.x * w4.x + r.y * w4.y + r.z * w4.z + r.w * w4.w;
            #pragma unroll
            for (int off = 16; off; off >>= 1)
                p += __shfl_xor_sync(0xffffffffu, p, off);
            if (lane == 0) {
                atomicAdd(&g_delta[(size_t)b * N + n], alpha[n] * p);
                atomicOr(&g_flag[n], 1u << b);
            }
        }
    }
}

// ---------------- K3: main sweep, fused beta-set + delta-add ----------------
// 256 threads / block, 128 nodes / block. Warp handles 16 nodes in 2 passes
// of 8 outstanding float4 row loads (deep MLP to hide DRAM latency).
__global__ __launch_bounds__(256)
void main_kernel(const float* __restrict__ set_table,
                 const float* __restrict__ alpha,
                 float* __restrict__ out, int N, int Bn)
{
    __shared__ float    sh_s[128];
    __shared__ float    sh_a[128];
    __shared__ unsigned sh_f[128];
    __shared__ float    sh_U[16];
    int tid = threadIdx.x;
    int lane = tid & 31, warp = tid >> 5;
    int base = blockIdx.x * 128;

    if (tid < Bn) sh_U[tid] = g_U[tid];
    if (tid < 128) {
        int n = base + tid;
        sh_a[tid] = (n < N) ? alpha[n] : 0.f;
        sh_f[tid] = (n < N) ? g_flag[n] : 0u;
    }
    float4 v4 = reinterpret_cast<const float4*>(g_v)[lane];
    float cval = g_c;

    #pragma unroll
    for (int pass = 0; pass < 2; ++pass) {
        int n0 = base + warp * 16 + pass * 8;
        float4 r[8];
        #pragma unroll
        for (int i = 0; i < 8; ++i) {
            int n = n0 + i;
            r[i] = (n < N)
                 ? reinterpret_cast<const float4*>(set_table + (size_t)n * 128)[lane]
                 : make_float4(0.f, 0.f, 0.f, 0.f);
        }
        #pragma unroll
        for (int i = 0; i < 8; ++i) {
            float p = r[i].x * v4.x + r[i].y * v4.y + r[i].z * v4.z + r[i].w * v4.w;
            #pragma unroll
            for (int off = 16; off; off >>= 1)
                p += __shfl_xor_sync(0xffffffffu, p, off);
            if (lane == 0)
                sh_s[warp * 16 + pass * 8 + i] = p + cval;
        }
    }
    __syncthreads();

    int count = N - base; if (count > 128) count = 128;
    #pragma unroll 4
    for (int idx = tid; idx < Bn * 128; idx += 256) {
        int b = idx >> 7, j = idx & 127;
        if (j < count) {
            float s = sh_s[j];
            float val = s + sh_U[b];
            if ((sh_f[j] >> b) & 1u)
                val = (1.f - sh_a[j]) * s + sh_U[b]
                    + g_delta[(size_t)b * N + base + j];
            out[(size_t)b * N + base + j] = val;
        }
    }
}

// ---------------- host launch ----------------
extern "C" void kernel_launch(void* const* d_in, const int* in_sizes, int n_in,
                              void* d_out, int out_size)
{
    int iUE, iSE, iRFE, iHIS, iNOW, iUID, iUET, iSET, iPW, iPB, iTH, iAL,
        iW1, iB1, iW2, iB2, iWST, iBST, iWU, iBU;
    if (in_sizes[3] < 100000) {
        iUE=0; iSE=1; iRFE=2; iHIS=3; iNOW=4; iUID=5; iUET=6; iSET=7; iPW=8; iPB=9;
        iTH=10; iAL=11; iW1=12; iB1=13; iW2=14; iB2=15; iWST=16; iBST=17; iWU=18; iBU=19;
    } else {
        iUE=0; iSE=1; iRFE=2; iUET=3; iSET=4; iPW=5; iPB=6; iTH=7; iAL=8; iW1=9;
        iB1=10; iW2=11; iB2=12; iWST=13; iBST=14; iWU=15; iBU=16; iHIS=17; iNOW=18; iUID=19;
    }

    const float* user_embedding    = (const float*)d_in[iUE];
    const float* station_embedding = (const float*)d_in[iSE];
    const float* raw_field_embed   = (const float*)d_in[iRFE];
    const float* user_emb_table    = (const float*)d_in[iUET];
    const float* station_emb_table = (const float*)d_in[iSET];
    const float* proj_w            = (const float*)d_in[iPW];
    const float* proj_b            = (const float*)d_in[iPB];
    const float* theta             = (const float*)d_in[iTH];
    const float* alpha             = (const float*)d_in[iAL];
    const float* w_his1            = (const float*)d_in[iW1];
    const float* b_his1            = (const float*)d_in[iB1];
    const float* w_his2            = (const float*)d_in[iW2];
    const float* b_his2            = (const float*)d_in[iB2];
    const float* w_st              = (const float*)d_in[iWST];
    const float* b_st              = (const float*)d_in[iBST];
    const float* w_u               = (const float*)d_in[iWU];
    const float* b_u               = (const float*)d_in[iBU];
    const int*   his_nodes         = (const int*)d_in[iHIS];
    const int*   now_nodes         = (const int*)d_in[iNOW];
    const int*   user_id           = (const int*)d_in[iUID];

    int B  = in_sizes[iUE] / 128;     // 8
    int N  = in_sizes[iAL];           // 60082
    int BK = in_sizes[iHIS];          // 256
    int K  = BK / B;                  // 32

    float* out = (float*)d_out;
    (void)out_size; (void)n_in;

    // K1: prep + scattered zeroing
    int zBlocks = (2 * BK + 255) / 256;
    prep_zero_kernel<<<1 + zBlocks, 256>>>(proj_w, proj_b, w_his2, b_his2, w_st, b_st,
                                           w_u, b_u, user_embedding, user_emb_table,
                                           theta, user_id, now_nodes, his_nodes,
                                           B, N, K, BK);

    // K2: corrections
    int hisBlocks = (BK + 31) / 32;
    int nowBlocks = (BK + 31) / 32;
    corr_kernel<<<hisBlocks + nowBlocks, 256>>>(now_nodes, his_nodes, alpha,
                                                station_embedding, raw_field_embed,
                                                w_st, w_his1, b_his1,
                                                N, K, BK, hisBlocks);

    // K3: main sweep with fused scatter application
    int grid = (N + 127) / 128;
    main_kernel<<<grid, 256>>>(station_emb_table, alpha, out, N, B);
}

// round 3
// speedup vs baseline: 1.6671x; 1.6671x over previous
#include <cuda_runtime.h>
#include <cstddef>

// ---------------- device scratch (no allocations allowed) ----------------
#define MAX_N 262144
__device__ float    g_v[128];           // proj_w @ w_st
__device__ float    g_u[64];            // w_his2 @ w_st
__device__ float    g_U[16];            // user_out[b] + b_u + b_st
__device__ float    g_c;                // proj_b · w_st
__device__ float    g_bh2;              // b_his2 · w_st
__device__ float    g_delta[1 << 20];   // per-(b,n) scattered correction (4 MB)
__device__ unsigned g_flag[MAX_N];      // per-n batch bitmask

__device__ __forceinline__ float warp_sum(float p) {
    #pragma unroll
    for (int off = 16; off; off >>= 1)
        p += __shfl_xor_sync(0xffffffffu, p, off);
    return p;
}

// ---------------- K1: warp-parallel prep + scattered zeroing ----------------
// block 0: g_v (8 warps x 16 rows, 4-deep load groups)
// block 1: g_u (8 warps x 8 rows) + g_c + g_bh2
// block 2: g_U (warp per batch element)
// blocks 3+: zero the delta/flag spots this run touches
__global__ __launch_bounds__(256)
void prep_zero_kernel(const float* __restrict__ proj_w,
                      const float* __restrict__ proj_b,
                      const float* __restrict__ w_his2,
                      const float* __restrict__ b_his2,
                      const float* __restrict__ w_st,
                      const float* __restrict__ b_st,
                      const float* __restrict__ w_u,
                      const float* __restrict__ b_u,
                      const float* __restrict__ user_embedding,
                      const float* __restrict__ user_emb_table,
                      const float* __restrict__ theta,
                      const int* __restrict__ user_id,
                      const int* __restrict__ now_nodes,
                      const int* __restrict__ his_nodes,
                      int Bn, int N, int K, int BK)
{
    int tid  = threadIdx.x;
    int lane = tid & 31, warp = tid >> 5;

    if (blockIdx.x == 0) {
        // g_v[r] = proj_w[r,:] . w_st
        float4 wv = reinterpret_cast<const float4*>(w_st)[lane];
        #pragma unroll
        for (int g = 0; g < 4; ++g) {
            int r0 = warp * 16 + g * 4;
            float4 a[4];
            #pragma unroll
            for (int i = 0; i < 4; ++i)
                a[i] = reinterpret_cast<const float4*>(proj_w + (r0 + i) * 128)[lane];
            #pragma unroll
            for (int i = 0; i < 4; ++i) {
                float p = a[i].x * wv.x + a[i].y * wv.y + a[i].z * wv.z + a[i].w * wv.w;
                p = warp_sum(p);
                if (lane == 0) g_v[r0 + i] = p;
            }
        }
    } else if (blockIdx.x == 1) {
        // g_u[j] = w_his2[j,:] . w_st ; g_c = proj_b . w_st ; g_bh2 = b_his2 . w_st
        float4 wv = reinterpret_cast<const float4*>(w_st)[lane];
        #pragma unroll
        for (int g = 0; g < 2; ++g) {
            int r0 = warp * 8 + g * 4;
            float4 a[4];
            #pragma unroll
            for (int i = 0; i < 4; ++i)
                a[i] = reinterpret_cast<const float4*>(w_his2 + (r0 + i) * 128)[lane];
            #pragma unroll
            for (int i = 0; i < 4; ++i) {
                float p = a[i].x * wv.x + a[i].y * wv.y + a[i].z * wv.z + a[i].w * wv.w;
                p = warp_sum(p);
                if (lane == 0) g_u[r0 + i] = p;
            }
        }
        if (warp == 0) {
            float4 pb = reinterpret_cast<const float4*>(proj_b)[lane];
            float p = pb.x * wv.x + pb.y * wv.y + pb.z * wv.z + pb.w * wv.w;
            p = warp_sum(p);
            if (lane == 0) g_c = p;
        } else if (warp == 1) {
            float4 bh = reinterpret_cast<const float4*>(b_his2)[lane];
            float p = bh.x * wv.x + bh.y * wv.y + bh.z * wv.z + bh.w * wv.w;
            p = warp_sum(p);
            if (lane == 0) g_bh2 = p;
        }
    } else if (blockIdx.x == 2) {
        // g_U[b] = user_mem[b] . w_u + b_u + b_st, warp per b
        int b = warp;
        if (b < Bn) {
            int uid = user_id[b];
            float th = theta[uid];
            float4 ue = reinterpret_cast<const float4*>(user_embedding + b * 128)[lane];
            float4 ut = reinterpret_cast<const float4*>(user_emb_table + (size_t)uid * 128)[lane];
            float4 wu = reinterpret_cast<const float4*>(w_u)[lane];
            float p = ((1.f - th) * ue.x + th * ut.x) * wu.x
                    + ((1.f - th) * ue.y + th * ut.y) * wu.y
                    + ((1.f - th) * ue.z + th * ut.z) * wu.z
                    + ((1.f - th) * ue.w + th * ut.w) * wu.w;
            p = warp_sum(p);
            if (lane == 0) g_U[b] = p + b_u[0] + b_st[0];
        }
    } else {
        int t = (blockIdx.x - 3) * blockDim.x + tid;
        if (t < 2 * BK) {
            int which = t / BK, r = t - which * BK;
            int n = which ? his_nodes[r] : now_nodes[r];
            int b = r / K;
            g_flag[n] = 0u;
            g_delta[(size_t)b * N + n] = 0.f;
        }
    }
}

// ---------------- K2: corrections into g_delta / g_flag ----------------
__global__ __launch_bounds__(256)
void corr_kernel(const int* __restrict__ now_nodes,
                 const int* __restrict__ his_nodes,
                 const float* __restrict__ alpha,
                 const float* __restrict__ station_embedding,
                 const float* __restrict__ raw_field_embed,
                 const float* __restrict__ w_st,
                 const float* __restrict__ w_his1,
                 const float* __restrict__ b_his1,
                 int N, int K, int BK, int hisBlocks)
{
    __shared__ float w1s[128 * 64];      // 32 KB
    __shared__ float xs[8][128];
    int tid = threadIdx.x;
    int lane = tid & 31, warp = tid >> 5;

    if (blockIdx.x < hisBlocks) {
        #pragma unroll 4
        for (int i = tid; i < 128 * 64; i += 256) w1s[i] = w_his1[i];
        __syncthreads();

        float b0 = b_his1[lane], b1 = b_his1[lane + 32];
        float u0 = g_u[lane],    u1 = g_u[lane + 32];
        float bh2 = g_bh2;

        #pragma unroll
        for (int i = 0; i < 4; ++i) {
            int e = blockIdx.x * 32 + warp * 4 + i;
            if (e >= BK) break;
            int n = his_nodes[e], b = e / K;
            float4 xv = reinterpret_cast<const float4*>(
                            raw_field_embed + (size_t)n * 128)[lane];
            reinterpret_cast<float4*>(xs[warp])[lane] = xv;
            __syncwarp();
            float a0 = b0, a1 = b1;
            #pragma unroll 8
            for (int d = 0; d < 128; ++d) {
                float x = xs[warp][d];
                a0 += x * w1s[d * 64 + lane];
                a1 += x * w1s[d * 64 + lane + 32];
            }
            float l0 = a0 > 0.f ? a0 : 0.01f * a0;
            float l1 = a1 > 0.f ? a1 : 0.01f * a1;
            float val = warp_sum(l0 * u0 + l1 * u1);
            if (lane == 0) {
                atomicAdd(&g_delta[(size_t)b * N + n], alpha[n] * (val + bh2));
                atomicOr(&g_flag[n], 1u << b);
            }
            __syncwarp();
        }
    } else {
        int bb = blockIdx.x - hisBlocks;
        float4 w4 = reinterpret_cast<const float4*>(w_st)[lane];
        #pragma unroll
        for (int i = 0; i < 4; ++i) {
            int e = bb * 32 + warp * 4 + i;
            if (e >= BK) break;
            int n = now_nodes[e], b = e / K;
            float4 r = reinterpret_cast<const float4*>(
                           station_embedding + (size_t)n * 128)[lane];
            float p = warp_sum(r.x * w4.x + r.y * w4.y + r.z * w4.z + r.w * w4.w);
            if (lane == 0) {
                atomicAdd(&g_delta[(size_t)b * N + n], alpha[n] * p);
                atomicOr(&g_flag[n], 1u << b);
            }
        }
    }
}

// ---------------- K3: main sweep, fused beta-set + delta-add ----------------
__global__ __launch_bounds__(256)
void main_kernel(const float* __restrict__ set_table,
                 const float* __restrict__ alpha,
                 float* __restrict__ out, int N, int Bn)
{
    __shared__ float    sh_s[128];
    __shared__ float    sh_a[128];
    __shared__ unsigned sh_f[128];
    __shared__ float    sh_U[16];
    int tid = threadIdx.x;
    int lane = tid & 31, warp = tid >> 5;
    int base = blockIdx.x * 128;

    if (tid < Bn) sh_U[tid] = g_U[tid];
    if (tid < 128) {
        int n = base + tid;
        sh_a[tid] = (n < N) ? alpha[n] : 0.f;
        sh_f[tid] = (n < N) ? g_flag[n] : 0u;
    }
    float4 v4 = reinterpret_cast<const float4*>(g_v)[lane];
    float cval = g_c;

    #pragma unroll
    for (int pass = 0; pass < 2; ++pass) {
        int n0 = base + warp * 16 + pass * 8;
        float4 r[8];
        #pragma unroll
        for (int i = 0; i < 8; ++i) {
            int n = n0 + i;
            r[i] = (n < N)
                 ? reinterpret_cast<const float4*>(set_table + (size_t)n * 128)[lane]
                 : make_float4(0.f, 0.f, 0.f, 0.f);
        }
        #pragma unroll
        for (int i = 0; i < 8; ++i) {
            float p = warp_sum(r[i].x * v4.x + r[i].y * v4.y + r[i].z * v4.z + r[i].w * v4.w);
            if (lane == 0)
                sh_s[warp * 16 + pass * 8 + i] = p + cval;
        }
    }
    __syncthreads();

    int count = N - base; if (count > 128) count = 128;
    #pragma unroll 4
    for (int idx = tid; idx < Bn * 128; idx += 256) {
        int b = idx >> 7, j = idx & 127;
        if (j < count) {
            float s = sh_s[j];
            float val = s + sh_U[b];
            if ((sh_f[j] >> b) & 1u)
                val = (1.f - sh_a[j]) * s + sh_U[b]
                    + g_delta[(size_t)b * N + base + j];
            out[(size_t)b * N + base + j] = val;
        }
    }
}

// ---------------- host launch ----------------
extern "C" void kernel_launch(void* const* d_in, const int* in_sizes, int n_in,
                              void* d_out, int out_size)
{
    int iUE, iSE, iRFE, iHIS, iNOW, iUID, iUET, iSET, iPW, iPB, iTH, iAL,
        iW1, iB1, iW2, iB2, iWST, iBST, iWU, iBU;
    if (in_sizes[3] < 100000) {
        iUE=0; iSE=1; iRFE=2; iHIS=3; iNOW=4; iUID=5; iUET=6; iSET=7; iPW=8; iPB=9;
        iTH=10; iAL=11; iW1=12; iB1=13; iW2=14; iB2=15; iWST=16; iBST=17; iWU=18; iBU=19;
    } else {
        iUE=0; iSE=1; iRFE=2; iUET=3; iSET=4; iPW=5; iPB=6; iTH=7; iAL=8; iW1=9;
        iB1=10; iW2=11; iB2=12; iWST=13; iBST=14; iWU=15; iBU=16; iHIS=17; iNOW=18; iUID=19;
    }

    const float* user_embedding    = (const float*)d_in[iUE];
    const float* station_embedding = (const float*)d_in[iSE];
    const float* raw_field_embed   = (const float*)d_in[iRFE];
    const float* user_emb_table    = (const float*)d_in[iUET];
    const float* station_emb_table = (const float*)d_in[iSET];
    const float* proj_w            = (const float*)d_in[iPW];
    const float* proj_b            = (const float*)d_in[iPB];
    const float* theta             = (const float*)d_in[iTH];
    const float* alpha             = (const float*)d_in[iAL];
    const float* w_his1            = (const float*)d_in[iW1];
    const float* b_his1            = (const float*)d_in[iB1];
    const float* w_his2            = (const float*)d_in[iW2];
    const float* b_his2            = (const float*)d_in[iB2];
    const float* w_st              = (const float*)d_in[iWST];
    const float* b_st              = (const float*)d_in[iBST];
    const float* w_u               = (const float*)d_in[iWU];
    const float* b_u               = (const float*)d_in[iBU];
    const int*   his_nodes         = (const int*)d_in[iHIS];
    const int*   now_nodes         = (const int*)d_in[iNOW];
    const int*   user_id           = (const int*)d_in[iUID];

    int B  = in_sizes[iUE] / 128;     // 8
    int N  = in_sizes[iAL];           // 60082
    int BK = in_sizes[iHIS];          // 256
    int K  = BK / B;                  // 32

    float* out = (float*)d_out;
    (void)out_size; (void)n_in;

    // K1: warp-parallel prep + scattered zeroing
    int zBlocks = (2 * BK + 255) / 256;
    prep_zero_kernel<<<3 + zBlocks, 256>>>(proj_w, proj_b, w_his2, b_his2, w_st, b_st,
                                           w_u, b_u, user_embedding, user_emb_table,
                                           theta, user_id, now_nodes, his_nodes,
                                           B, N, K, BK);

    // K2: corrections
    int hisBlocks = (BK + 31) / 32;
    int nowBlocks = (BK + 31) / 32;
    corr_kernel<<<hisBlocks + nowBlocks, 256>>>(now_nodes, his_nodes, alpha,
                                                station_embedding, raw_field_embed,
                                                w_st, w_his1, b_his1,
                                                N, K, BK, hisBlocks);

    // K3: main sweep with fused scatter application
    int grid = (N + 127) / 128;
    main_kernel<<<grid, 256>>>(station_emb_table, alpha, out, N, B);
}

// round 4
// speedup vs baseline: 1.7753x; 1.0649x over previous
#include <cuda_runtime.h>
#include <cstddef>

// ---------------- device scratch (zero-initialized at load; consume-and-clear keeps it zeroed) ----------------
#define MAX_N 262144
__device__ float    g_v[128];           // proj_w @ w_st
__device__ float    g_U[16];            // user_out[b] + b_u + b_st
__device__ float    g_c;                // proj_b · w_st
__device__ float    g_delta[1 << 20];   // per-(b,n) scattered correction (4 MB, stays zero except in-flight)
__device__ unsigned g_flag[MAX_N];      // per-n batch bitmask (stays zero except in-flight)

__device__ __forceinline__ float warp_sum(float p) {
    #pragma unroll
    for (int off = 16; off; off >>= 1)
        p += __shfl_xor_sync(0xffffffffu, p, off);
    return p;
}

// ---------------- K1: fused prep + corrections ----------------
// blocks [0, hisBlocks): his MLP entries (self-contained: compute u, bh2 in-block)
// blocks [hisBlocks, hisBlocks+nowBlocks): now dot entries
// block  [last]: g_v / g_U / g_c prep
__global__ __launch_bounds__(256)
void k1_kernel(const int* __restrict__ now_nodes,
               const int* __restrict__ his_nodes,
               const float* __restrict__ alpha,
               const float* __restrict__ station_embedding,
               const float* __restrict__ raw_field_embed,
               const float* __restrict__ w_st,
               const float* __restrict__ w_his1,
               const float* __restrict__ b_his1,
               const float* __restrict__ w_his2,
               const float* __restrict__ b_his2,
               const float* __restrict__ proj_w,
               const float* __restrict__ proj_b,
               const float* __restrict__ w_u,
               const float* __restrict__ b_u,
               const float* __restrict__ b_st,
               const float* __restrict__ user_embedding,
               const float* __restrict__ user_emb_table,
               const float* __restrict__ theta,
               const int* __restrict__ user_id,
               int Bn, int N, int K, int BK, int hisBlocks, int nowBlocks)
{
    int tid  = threadIdx.x;
    int lane = tid & 31, warp = tid >> 5;

    if (blockIdx.x < (unsigned)hisBlocks) {
        // ---- his MLP correction entries ----
        __shared__ float w1s[128 * 64];     // 32 KB
        __shared__ float xs[8][128];        // 4 KB
        __shared__ float us[64];
        __shared__ float sh_bh2;

        // stage w_his1
        #pragma unroll 4
        for (int i = tid; i < 128 * 64; i += 256) w1s[i] = w_his1[i];

        // compute u[j] = w_his2[j,:]·w_st cooperatively (warp per 8 rows)
        float4 wv = reinterpret_cast<const float4*>(w_st)[lane];
        #pragma unroll
        for (int g = 0; g < 2; ++g) {
            int r0 = warp * 8 + g * 4;
            float4 a[4];
            #pragma unroll
            for (int i = 0; i < 4; ++i)
                a[i] = reinterpret_cast<const float4*>(w_his2 + (r0 + i) * 128)[lane];
            #pragma unroll
            for (int i = 0; i < 4; ++i) {
                float p = warp_sum(a[i].x * wv.x + a[i].y * wv.y + a[i].z * wv.z + a[i].w * wv.w);
                if (lane == 0) us[r0 + i] = p;
            }
        }
        if (warp == 0) {
            float4 bh = reinterpret_cast<const float4*>(b_his2)[lane];
            float p = warp_sum(bh.x * wv.x + bh.y * wv.y + bh.z * wv.z + bh.w * wv.w);
            if (lane == 0) sh_bh2 = p;
        }
        __syncthreads();

        float b0 = b_his1[lane], b1 = b_his1[lane + 32];
        float u0 = us[lane],     u1 = us[lane + 32];
        float bh2 = sh_bh2;

        #pragma unroll
        for (int i = 0; i < 4; ++i) {
            int e = blockIdx.x * 32 + warp * 4 + i;
            if (e >= BK) break;
            int n = his_nodes[e], b = e / K;
            float4 xv = reinterpret_cast<const float4*>(
                            raw_field_embed + (size_t)n * 128)[lane];
            reinterpret_cast<float4*>(xs[warp])[lane] = xv;
            __syncwarp();
            float a0 = b0, a1 = b1;
            #pragma unroll 8
            for (int d = 0; d < 128; ++d) {
                float x = xs[warp][d];
                a0 += x * w1s[d * 64 + lane];
                a1 += x * w1s[d * 64 + lane + 32];
            }
            float l0 = a0 > 0.f ? a0 : 0.01f * a0;
            float l1 = a1 > 0.f ? a1 : 0.01f * a1;
            float val = warp_sum(l0 * u0 + l1 * u1);
            if (lane == 0) {
                atomicAdd(&g_delta[(size_t)b * N + n], alpha[n] * (val + bh2));
                atomicOr(&g_flag[n], 1u << b);
            }
            __syncwarp();
        }
    } else if (blockIdx.x < (unsigned)(hisBlocks + nowBlocks)) {
        // ---- now dot-product correction entries ----
        int bb = blockIdx.x - hisBlocks;
        float4 w4 = reinterpret_cast<const float4*>(w_st)[lane];
        #pragma unroll
        for (int i = 0; i < 4; ++i) {
            int e = bb * 32 + warp * 4 + i;
            if (e >= BK) break;
            int n = now_nodes[e], b = e / K;
            float4 r = reinterpret_cast<const float4*>(
                           station_embedding + (size_t)n * 128)[lane];
            float p = warp_sum(r.x * w4.x + r.y * w4.y + r.z * w4.z + r.w * w4.w);
            if (lane == 0) {
                atomicAdd(&g_delta[(size_t)b * N + n], alpha[n] * p);
                atomicOr(&g_flag[n], 1u << b);
            }
        }
    } else {
        // ---- prep: g_v, g_U, g_c ----
        float4 wv = reinterpret_cast<const float4*>(w_st)[lane];
        #pragma unroll
        for (int g = 0; g < 4; ++g) {
            int r0 = warp * 16 + g * 4;
            float4 a[4];
            #pragma unroll
            for (int i = 0; i < 4; ++i)
                a[i] = reinterpret_cast<const float4*>(proj_w + (r0 + i) * 128)[lane];
            #pragma unroll
            for (int i = 0; i < 4; ++i) {
                float p = warp_sum(a[i].x * wv.x + a[i].y * wv.y + a[i].z * wv.z + a[i].w * wv.w);
                if (lane == 0) g_v[r0 + i] = p;
            }
        }
        int b = warp;
        if (b < Bn) {
            int uid = user_id[b];
            float th = theta[uid];
            float4 ue = reinterpret_cast<const float4*>(user_embedding + b * 128)[lane];
            float4 ut = reinterpret_cast<const float4*>(user_emb_table + (size_t)uid * 128)[lane];
            float4 wu = reinterpret_cast<const float4*>(w_u)[lane];
            float p = ((1.f - th) * ue.x + th * ut.x) * wu.x
                    + ((1.f - th) * ue.y + th * ut.y) * wu.y
                    + ((1.f - th) * ue.z + th * ut.z) * wu.z
                    + ((1.f - th) * ue.w + th * ut.w) * wu.w;
            p = warp_sum(p);
            if (lane == 0) g_U[b] = p + b_u[0] + b_st[0];
        }
        if (warp == 0) {
            float4 pb = reinterpret_cast<const float4*>(proj_b)[lane];
            float p = warp_sum(pb.x * wv.x + pb.y * wv.y + pb.z * wv.z + pb.w * wv.w);
            if (lane == 0) g_c = p;
        }
    }
}

// ---------------- K2: main sweep, fused beta-set + delta-add, consume-and-clear ----------------
__global__ __launch_bounds__(256)
void main_kernel(const float* __restrict__ set_table,
                 const float* __restrict__ alpha,
                 float* __restrict__ out, int N, int Bn)
{
    __shared__ float    sh_s[128];
    __shared__ unsigned sh_f[128];
    __shared__ float    sh_U[16];
    int tid = threadIdx.x;
    int lane = tid & 31, warp = tid >> 5;
    int base = blockIdx.x * 128;

    if (tid < Bn) sh_U[tid] = g_U[tid];
    if (tid < 128) {
        int n = base + tid;
        sh_f[tid] = (n < N) ? g_flag[n] : 0u;
    }
    float4 v4 = reinterpret_cast<const float4*>(g_v)[lane];
    float cval = g_c;

    #pragma unroll
    for (int pass = 0; pass < 2; ++pass) {
        int n0 = base + warp * 16 + pass * 8;
        float4 r[8];
        #pragma unroll
        for (int i = 0; i < 8; ++i) {
            int n = n0 + i;
            r[i] = (n < N)
                 ? reinterpret_cast<const float4*>(set_table + (size_t)n * 128)[lane]
                 : make_float4(0.f, 0.f, 0.f, 0.f);
        }
        #pragma unroll
        for (int i = 0; i < 8; ++i) {
            float p = warp_sum(r[i].x * v4.x + r[i].y * v4.y + r[i].z * v4.z + r[i].w * v4.w);
            if (lane == 0)
                sh_s[warp * 16 + pass * 8 + i] = p + cval;
        }
    }
    __syncthreads();

    int count = N - base; if (count > 128) count = 128;
    #pragma unroll 4
    for (int idx = tid; idx < Bn * 128; idx += 256) {
        int b = idx >> 7, j = idx & 127;
        if (j < count) {
            int n = base + j;
            float s = sh_s[j];
            float val = s + sh_U[b];
            unsigned f = sh_f[j];
            if (f) {
                if ((f >> b) & 1u) {
                    val = (1.f - alpha[n]) * s + sh_U[b] + g_delta[(size_t)b * N + n];
                    g_delta[(size_t)b * N + n] = 0.f;   // restore zero for next replay
                }
                if (b == 0) g_flag[n] = 0u;             // restore zero for next replay
            }
            out[(size_t)b * N + n] = val;
        }
    }
}

// ---------------- host launch ----------------
extern "C" void kernel_launch(void* const* d_in, const int* in_sizes, int n_in,
                              void* d_out, int out_size)
{
    int iUE, iSE, iRFE, iHIS, iNOW, iUID, iUET, iSET, iPW, iPB, iTH, iAL,
        iW1, iB1, iW2, iB2, iWST, iBST, iWU, iBU;
    if (in_sizes[3] < 100000) {
        iUE=0; iSE=1; iRFE=2; iHIS=3; iNOW=4; iUID=5; iUET=6; iSET=7; iPW=8; iPB=9;
        iTH=10; iAL=11; iW1=12; iB1=13; iW2=14; iB2=15; iWST=16; iBST=17; iWU=18; iBU=19;
    } else {
        iUE=0; iSE=1; iRFE=2; iUET=3; iSET=4; iPW=5; iPB=6; iTH=7; iAL=8; iW1=9;
        iB1=10; iW2=11; iB2=12; iWST=13; iBST=14; iWU=15; iBU=16; iHIS=17; iNOW=18; iUID=19;
    }

    const float* user_embedding    = (const float*)d_in[iUE];
    const float* station_embedding = (const float*)d_in[iSE];
    const float* raw_field_embed   = (const float*)d_in[iRFE];
    const float* user_emb_table    = (const float*)d_in[iUET];
    const float* station_emb_table = (const float*)d_in[iSET];
    const float* proj_w            = (const float*)d_in[iPW];
    const float* proj_b            = (const float*)d_in[iPB];
    const float* theta             = (const float*)d_in[iTH];
    const float* alpha             = (const float*)d_in[iAL];
    const float* w_his1            = (const float*)d_in[iW1];
    const float* b_his1            = (const float*)d_in[iB1];
    const float* w_his2            = (const float*)d_in[iW2];
    const float* b_his2            = (const float*)d_in[iB2];
    const float* w_st              = (const float*)d_in[iWST];
    const float* b_st              = (const float*)d_in[iBST];
    const float* w_u               = (const float*)d_in[iWU];
    const float* b_u               = (const float*)d_in[iBU];
    const int*   his_nodes         = (const int*)d_in[iHIS];
    const int*   now_nodes         = (const int*)d_in[iNOW];
    const int*   user_id           = (const int*)d_in[iUID];

    int B  = in_sizes[iUE] / 128;     // 8
    int N  = in_sizes[iAL];           // 60082
    int BK = in_sizes[iHIS];          // 256
    int K  = BK / B;                  // 32

    float* out = (float*)d_out;
    (void)out_size; (void)n_in;

    // K1: fused prep + corrections (all blocks independent, one wave)
    int hisBlocks = (BK + 31) / 32;
    int nowBlocks = (BK + 31) / 32;
    k1_kernel<<<hisBlocks + nowBlocks + 1, 256>>>(
        now_nodes, his_nodes, alpha, station_embedding, raw_field_embed,
        w_st, w_his1, b_his1, w_his2, b_his2, proj_w, proj_b,
        w_u, b_u, b_st, user_embedding, user_emb_table, theta, user_id,
        B, N, K, BK, hisBlocks, nowBlocks);

    // K2: main sweep with fused scatter application + state restore
    int grid = (N + 127) / 128;
    main_kernel<<<grid, 256>>>(station_emb_table, alpha, out, N, B);
}

// round 5
// speedup vs baseline: 1.7942x; 1.0107x over previous
#include <cuda_runtime.h>
#include <cstddef>

// ---------------- device scratch (zero-initialized at load; consume-and-clear keeps it zeroed) ----------------
#define MAX_N 262144
__device__ float    g_v[128];           // proj_w @ w_st
__device__ float    g_U[16];            // user_out[b] + b_u + b_st
__device__ float    g_c;                // proj_b · w_st
__device__ float    g_delta[1 << 20];   // per-(b,n) scattered correction (4 MB)
__device__ unsigned g_flag[MAX_N];      // per-n batch bitmask

__device__ __forceinline__ float warp_sum(float p) {
    #pragma unroll
    for (int off = 16; off; off >>= 1)
        p += __shfl_xor_sync(0xffffffffu, p, off);
    return p;
}

// ---------------- K1: fused prep + corrections (unchanged from R4) ----------------
__global__ __launch_bounds__(256)
void k1_kernel(const int* __restrict__ now_nodes,
               const int* __restrict__ his_nodes,
               const float* __restrict__ alpha,
               const float* __restrict__ station_embedding,
               const float* __restrict__ raw_field_embed,
               const float* __restrict__ w_st,
               const float* __restrict__ w_his1,
               const float* __restrict__ b_his1,
               const float* __restrict__ w_his2,
               const float* __restrict__ b_his2,
               const float* __restrict__ proj_w,
               const float* __restrict__ proj_b,
               const float* __restrict__ w_u,
               const float* __restrict__ b_u,
               const float* __restrict__ b_st,
               const float* __restrict__ user_embedding,
               const float* __restrict__ user_emb_table,
               const float* __restrict__ theta,
               const int* __restrict__ user_id,
               int Bn, int N, int K, int BK, int hisBlocks, int nowBlocks)
{
    int tid  = threadIdx.x;
    int lane = tid & 31, warp = tid >> 5;

    if (blockIdx.x < (unsigned)hisBlocks) {
        __shared__ float w1s[128 * 64];     // 32 KB
        __shared__ float xs[8][128];
        __shared__ float us[64];
        __shared__ float sh_bh2;

        #pragma unroll 4
        for (int i = tid; i < 128 * 64; i += 256) w1s[i] = w_his1[i];

        float4 wv = reinterpret_cast<const float4*>(w_st)[lane];
        #pragma unroll
        for (int g = 0; g < 2; ++g) {
            int r0 = warp * 8 + g * 4;
            float4 a[4];
            #pragma unroll
            for (int i = 0; i < 4; ++i)
                a[i] = reinterpret_cast<const float4*>(w_his2 + (r0 + i) * 128)[lane];
            #pragma unroll
            for (int i = 0; i < 4; ++i) {
                float p = warp_sum(a[i].x * wv.x + a[i].y * wv.y + a[i].z * wv.z + a[i].w * wv.w);
                if (lane == 0) us[r0 + i] = p;
            }
        }
        if (warp == 0) {
            float4 bh = reinterpret_cast<const float4*>(b_his2)[lane];
            float p = warp_sum(bh.x * wv.x + bh.y * wv.y + bh.z * wv.z + bh.w * wv.w);
            if (lane == 0) sh_bh2 = p;
        }
        __syncthreads();

        float b0 = b_his1[lane], b1 = b_his1[lane + 32];
        float u0 = us[lane],     u1 = us[lane + 32];
        float bh2 = sh_bh2;

        #pragma unroll
        for (int i = 0; i < 4; ++i) {
            int e = blockIdx.x * 32 + warp * 4 + i;
            if (e >= BK) break;
            int n = his_nodes[e], b = e / K;
            float4 xv = reinterpret_cast<const float4*>(
                            raw_field_embed + (size_t)n * 128)[lane];
            reinterpret_cast<float4*>(xs[warp])[lane] = xv;
            __syncwarp();
            float a0 = b0, a1 = b1;
            #pragma unroll 8
            for (int d = 0; d < 128; ++d) {
                float x = xs[warp][d];
                a0 += x * w1s[d * 64 + lane];
                a1 += x * w1s[d * 64 + lane + 32];
            }
            float l0 = a0 > 0.f ? a0 : 0.01f * a0;
            float l1 = a1 > 0.f ? a1 : 0.01f * a1;
            float val = warp_sum(l0 * u0 + l1 * u1);
            if (lane == 0) {
                atomicAdd(&g_delta[(size_t)b * N + n], alpha[n] * (val + bh2));
                atomicOr(&g_flag[n], 1u << b);
            }
            __syncwarp();
        }
    } else if (blockIdx.x < (unsigned)(hisBlocks + nowBlocks)) {
        int bb = blockIdx.x - hisBlocks;
        float4 w4 = reinterpret_cast<const float4*>(w_st)[lane];
        #pragma unroll
        for (int i = 0; i < 4; ++i) {
            int e = bb * 32 + warp * 4 + i;
            if (e >= BK) break;
            int n = now_nodes[e], b = e / K;
            float4 r = reinterpret_cast<const float4*>(
                           station_embedding + (size_t)n * 128)[lane];
            float p = warp_sum(r.x * w4.x + r.y * w4.y + r.z * w4.z + r.w * w4.w);
            if (lane == 0) {
                atomicAdd(&g_delta[(size_t)b * N + n], alpha[n] * p);
                atomicOr(&g_flag[n], 1u << b);
            }
        }
    } else {
        float4 wv = reinterpret_cast<const float4*>(w_st)[lane];
        #pragma unroll
        for (int g = 0; g < 4; ++g) {
            int r0 = warp * 16 + g * 4;
            float4 a[4];
            #pragma unroll
            for (int i = 0; i < 4; ++i)
                a[i] = reinterpret_cast<const float4*>(proj_w + (r0 + i) * 128)[lane];
            #pragma unroll
            for (int i = 0; i < 4; ++i) {
                float p = warp_sum(a[i].x * wv.x + a[i].y * wv.y + a[i].z * wv.z + a[i].w * wv.w);
                if (lane == 0) g_v[r0 + i] = p;
            }
        }
        int b = warp;
        if (b < Bn) {
            int uid = user_id[b];
            float th = theta[uid];
            float4 ue = reinterpret_cast<const float4*>(user_embedding + b * 128)[lane];
            float4 ut = reinterpret_cast<const float4*>(user_emb_table + (size_t)uid * 128)[lane];
            float4 wu = reinterpret_cast<const float4*>(w_u)[lane];
            float p = ((1.f - th) * ue.x + th * ut.x) * wu.x
                    + ((1.f - th) * ue.y + th * ut.y) * wu.y
                    + ((1.f - th) * ue.z + th * ut.z) * wu.z
                    + ((1.f - th) * ue.w + th * ut.w) * wu.w;
            p = warp_sum(p);
            if (lane == 0) g_U[b] = p + b_u[0] + b_st[0];
        }
        if (warp == 0) {
            float4 pb = reinterpret_cast<const float4*>(proj_b)[lane];
            float p = warp_sum(pb.x * wv.x + pb.y * wv.y + pb.z * wv.z + pb.w * wv.w);
            if (lane == 0) g_c = p;
        }
    }
}

// ---------------- K2: main sweep — 64 nodes/block for 2x grid / occupancy ----------------
__global__ __launch_bounds__(256)
void main_kernel(const float* __restrict__ set_table,
                 const float* __restrict__ alpha,
                 float* __restrict__ out, int N, int Bn)
{
    __shared__ float    sh_s[64];
    __shared__ unsigned sh_f[64];
    __shared__ float    sh_U[16];
    int tid = threadIdx.x;
    int lane = tid & 31, warp = tid >> 5;
    int base = blockIdx.x * 64;

    if (tid < Bn) sh_U[tid] = g_U[tid];
    if (tid < 64) {
        int n = base + tid;
        sh_f[tid] = (n < N) ? g_flag[n] : 0u;
    }
    float4 v4 = reinterpret_cast<const float4*>(g_v)[lane];
    float cval = g_c;

    // one pass: warp handles 8 rows, 8 outstanding float4 loads
    int n0 = base + warp * 8;
    float4 r[8];
    #pragma unroll
    for (int i = 0; i < 8; ++i) {
        int n = n0 + i;
        r[i] = (n < N)
             ? reinterpret_cast<const float4*>(set_table + (size_t)n * 128)[lane]
             : make_float4(0.f, 0.f, 0.f, 0.f);
    }
    #pragma unroll
    for (int i = 0; i < 8; ++i) {
        float p = warp_sum(r[i].x * v4.x + r[i].y * v4.y + r[i].z * v4.z + r[i].w * v4.w);
        if (lane == 0)
            sh_s[warp * 8 + i] = p + cval;
    }
    __syncthreads();

    int count = N - base; if (count > 64) count = 64;
    #pragma unroll
    for (int idx = tid; idx < Bn * 64; idx += 256) {
        int b = idx >> 6, j = idx & 63;
        if (j < count) {
            int n = base + j;
            float s = sh_s[j];
            float val = s + sh_U[b];
            unsigned f = sh_f[j];
            if (f) {
                if ((f >> b) & 1u) {
                    val = (1.f - alpha[n]) * s + sh_U[b] + g_delta[(size_t)b * N + n];
                    g_delta[(size_t)b * N + n] = 0.f;   // restore zero for next replay
                }
                if (b == 0) g_flag[n] = 0u;             // restore zero for next replay
            }
            out[(size_t)b * N + n] = val;
        }
    }
}

// ---------------- host launch ----------------
extern "C" void kernel_launch(void* const* d_in, const int* in_sizes, int n_in,
                              void* d_out, int out_size)
{
    int iUE, iSE, iRFE, iHIS, iNOW, iUID, iUET, iSET, iPW, iPB, iTH, iAL,
        iW1, iB1, iW2, iB2, iWST, iBST, iWU, iBU;
    if (in_sizes[3] < 100000) {
        iUE=0; iSE=1; iRFE=2; iHIS=3; iNOW=4; iUID=5; iUET=6; iSET=7; iPW=8; iPB=9;
        iTH=10; iAL=11; iW1=12; iB1=13; iW2=14; iB2=15; iWST=16; iBST=17; iWU=18; iBU=19;
    } else {
        iUE=0; iSE=1; iRFE=2; iUET=3; iSET=4; iPW=5; iPB=6; iTH=7; iAL=8; iW1=9;
        iB1=10; iW2=11; iB2=12; iWST=13; iBST=14; iWU=15; iBU=16; iHIS=17; iNOW=18; iUID=19;
    }

    const float* user_embedding    = (const float*)d_in[iUE];
    const float* station_embedding = (const float*)d_in[iSE];
    const float* raw_field_embed   = (const float*)d_in[iRFE];
    const float* user_emb_table    = (const float*)d_in[iUET];
    const float* station_emb_table = (const float*)d_in[iSET];
    const float* proj_w            = (const float*)d_in[iPW];
    const float* proj_b            = (const float*)d_in[iPB];
    const float* theta             = (const float*)d_in[iTH];
    const float* alpha             = (const float*)d_in[iAL];
    const float* w_his1            = (const float*)d_in[iW1];
    const float* b_his1            = (const float*)d_in[iB1];
    const float* w_his2            = (const float*)d_in[iW2];
    const float* b_his2            = (const float*)d_in[iB2];
    const float* w_st              = (const float*)d_in[iWST];
    const float* b_st              = (const float*)d_in[iBST];
    const float* w_u               = (const float*)d_in[iWU];
    const float* b_u               = (const float*)d_in[iBU];
    const int*   his_nodes         = (const int*)d_in[iHIS];
    const int*   now_nodes         = (const int*)d_in[iNOW];
    const int*   user_id           = (const int*)d_in[iUID];

    int B  = in_sizes[iUE] / 128;     // 8
    int N  = in_sizes[iAL];           // 60082
    int BK = in_sizes[iHIS];          // 256
    int K  = BK / B;                  // 32

    float* out = (float*)d_out;
    (void)out_size; (void)n_in;

    int hisBlocks = (BK + 31) / 32;
    int nowBlocks = (BK + 31) / 32;
    k1_kernel<<<hisBlocks + nowBlocks + 1, 256>>>(
        now_nodes, his_nodes, alpha, station_embedding, raw_field_embed,
        w_st, w_his1, b_his1, w_his2, b_his2, proj_w, proj_b,
        w_u, b_u, b_st, user_embedding, user_emb_table, theta, user_id,
        B, N, K, BK, hisBlocks, nowBlocks);

    int grid = (N + 63) / 64;
    main_kernel<<<grid, 256>>>(station_emb_table, alpha, out, N, B);
}